// round 13
// baseline (speedup 1.0000x reference)
#include <cuda_runtime.h>
#include <cstdint>

#define B_DIM    8
#define C_OUT    64
#define NK       7
#define GROUP_IN 4
#define C_IN     1792              // 64*4*7
#define L_DIM    4096
#define TILE     512
#define HALO     16                // covers |shift| <= 15
#define ROWW     (TILE + 2*HALO)   // 544 floats per staged row
#define ROWB     (ROWW * 4)        // 2176 bytes per staged row
#define NCH      (GROUP_IN * NK)   // 28 channels per c_out
#define QROWS    7                 // rows per quarter-buffer
#define QBUFB    (QROWS * ROWB)    // 15232 bytes per quarter slot
#define RING     4
#define THREADS  288               // 8 consumer warps + 1 producer warp
#define NCONS    256
#define CTAS_SM  3
#define GRID     (152 * CTAS_SM)   // 456 persistent CTAs
#define NTILES   (B_DIM * C_OUT * (L_DIM / TILE))   // 4096

// --- TMA bulk 1D: global -> shared, mbarrier transaction-counted ---
__device__ __forceinline__ void bulk_g2s(uint32_t dst, const void* src,
                                         unsigned bytes, uint32_t mbar) {
    asm volatile(
        "cp.async.bulk.shared::cluster.global.mbarrier::complete_tx::bytes "
        "[%0], [%1], %2, [%3];"
        :: "r"(dst), "l"(src), "r"(bytes), "r"(mbar) : "memory");
}
__device__ __forceinline__ void mbar_init(uint32_t mbar, unsigned cnt) {
    asm volatile("mbarrier.init.shared.b64 [%0], %1;" :: "r"(mbar), "r"(cnt) : "memory");
}
__device__ __forceinline__ void mbar_arrive_expect(uint32_t mbar, unsigned bytes) {
    asm volatile("mbarrier.arrive.expect_tx.shared.b64 _, [%0], %1;"
                 :: "r"(mbar), "r"(bytes) : "memory");
}
__device__ __forceinline__ void mbar_arrive(uint32_t mbar) {
    asm volatile("mbarrier.arrive.shared.b64 _, [%0];" :: "r"(mbar) : "memory");
}
__device__ __forceinline__ void mbar_wait(uint32_t mbar, unsigned ph) {
    asm volatile(
        "{\n\t.reg .pred P;\n\t"
        "LAB_%=:\n\t"
        "mbarrier.try_wait.parity.acquire.cta.shared::cta.b64 P, [%0], %1, 0x989680;\n\t"
        "@P bra.uni DONE_%=;\n\t"
        "bra.uni LAB_%=;\n\t"
        "DONE_%=:\n\t}"
        :: "r"(mbar), "r"(ph) : "memory");
}

__global__ __launch_bounds__(THREADS, CTAS_SM) void addshift_kernel(
    const float* __restrict__ x,
    const int*   __restrict__ si1,
    const int*   __restrict__ si2,
    const int*   __restrict__ si3,
    float*       __restrict__ out)
{
    extern __shared__ float sm[];                 // ring of 4 quarter-buffers
    __shared__ unsigned tab[C_OUT * NCH];         // packed per-(co,lc) offsets
    __shared__ int crel_s[NCH];                   // channel elem-offset per local row
    __shared__ __align__(8) unsigned long long mbar_s[2 * RING]; // tmb[4], cmb[4]

    const int tid = threadIdx.x;
    const uint32_t sm_base  = (uint32_t)__cvta_generic_to_shared(sm);
    const uint32_t tmb_base = (uint32_t)__cvta_generic_to_shared(&mbar_s[0]);
    const uint32_t cmb_base = (uint32_t)__cvta_generic_to_shared(&mbar_s[RING]);

    // ---- one-time tables (all 288 threads participate) ----
    if (tid < NCH)
        crel_s[tid] = ((tid / NK) * (C_OUT * NK) + tid % NK) * L_DIM;
    for (int c = tid; c < C_IN; c += THREADS) {
        int g  = c / (C_OUT * NK);
        int r  = c - g * (C_OUT * NK);
        int co = r / NK;
        int k  = r - co * NK;
        int lc = g * NK + k;
        unsigned o1 = 4u + 20u * (unsigned)(si1[c] % NK);
        unsigned o2 = 4u + 20u * (unsigned)(si2[c] % NK);
        unsigned o3 = 4u + 20u * (unsigned)(si3[c] % NK);
        tab[co * NCH + lc] = o1 | (o2 << 8) | (o3 << 16);
    }
    if (tid == 0) {
        #pragma unroll
        for (int s = 0; s < RING; ++s) {
            mbar_init(tmb_base + 8u * s, 32);      // producer-warp lanes
            mbar_init(cmb_base + 8u * s, NCONS);   // consumer threads
        }
    }
    __syncthreads();   // tables + mbarrier init visible; last bar.sync in kernel

    const unsigned OSZ = (unsigned)B_DIM * C_OUT * L_DIM;   // one output tensor

    if (tid >= NCONS) {
        // ================= PRODUCER (warp 8) =================
        const int ptid = tid - NCONS;             // lane 0..31
        unsigned qi = 0, cph = 0;
        for (int w = blockIdx.x; w < NTILES; w += GRID) {
            const int b   = w >> 9;
            const int rem = w & 511;
            const int co  = rem >> 3;
            const int tx  = rem & 7;
            const bool front = (tx == 0);
            const bool back  = (tx == 7);
            const unsigned sz = (front | back) ? (ROWB - 64u) : (unsigned)ROWB;
            const int gstart = (tx << 9) - HALO;
            const float* tbase = x + ((size_t)b * C_IN + (size_t)co * NK) * L_DIM
                               + gstart + (front ? HALO : 0);
            #pragma unroll
            for (int q = 0; q < 4; ++q) {
                const unsigned s = qi & 3u;
                if (qi >= RING) { mbar_wait(cmb_base + 8u * s, (cph >> s) & 1u); cph ^= 1u << s; }
                const uint32_t slotb = sm_base + s * (unsigned)QBUFB;
                // zero the 16-float OOB halo (bytes disjoint from bulk)
                if (front | back) {
                    uint32_t zb = slotb + (front ? 0u : (unsigned)((TILE + HALO) * 4));
                    if (ptid < QROWS * 4) {               // 28 float4 chunks
                        uint32_t a = zb + (unsigned)(ptid >> 2) * ROWB
                                   + (unsigned)(ptid & 3) * 16u;
                        asm volatile("st.shared.v4.b32 [%0], {%1,%1,%1,%1};"
                                     :: "r"(a), "r"(0) : "memory");
                    }
                }
                if (ptid == 0) mbar_arrive_expect(tmb_base + 8u * s, QROWS * sz);
                else           mbar_arrive(tmb_base + 8u * s);
                if (ptid < QROWS) {
                    const float* src = tbase + crel_s[q * QROWS + ptid];
                    bulk_g2s(slotb + (uint32_t)ptid * ROWB + (front ? 64u : 0u),
                             src, sz, tmb_base + 8u * s);
                }
                ++qi;
            }
        }
    } else {
        // ================= CONSUMERS (warps 0..7) =================
        unsigned qi = 0, tph = 0;
        const char* smc = (const char*)sm + (unsigned)tid * 4u;
        for (int w = blockIdx.x; w < NTILES; w += GRID) {
            const int b   = w >> 9;
            const int rem = w & 511;
            const int co  = rem >> 3;
            const int tx  = rem & 7;
            float a0 = 0.f, a1 = 0.f, a2 = 0.f, a3 = 0.f, a4 = 0.f, a5 = 0.f;
            #pragma unroll
            for (int q = 0; q < 4; ++q) {
                const unsigned s = qi & 3u;
                mbar_wait(tmb_base + 8u * s, (tph >> s) & 1u); tph ^= 1u << s;
                const unsigned* tp = tab + co * NCH + q * QROWS;
                const char* smb = smc + s * (unsigned)QBUFB;
                #pragma unroll
                for (int j = 0; j < QROWS; ++j) {
                    unsigned p = tp[j];                   // one LDS.32 broadcast
                    const char* r0 = smb + j * ROWB;
                    unsigned e1 = p & 255u;
                    unsigned e2 = (p >> 8) & 255u;
                    unsigned e3 = p >> 16;
                    a0 += *(const float*)(r0 + e1);
                    a1 += *(const float*)(r0 + e1 + 1024);
                    a2 += *(const float*)(r0 + e2);
                    a3 += *(const float*)(r0 + e2 + 1024);
                    a4 += *(const float*)(r0 + e3);
                    a5 += *(const float*)(r0 + e3 + 1024);
                }
                mbar_arrive(cmb_base + 8u * s);
                ++qi;
            }
            const unsigned ob = ((unsigned)(b * C_OUT + co)) * L_DIM + (tx << 9) + tid;
            out[ob]                 = a0;
            out[ob + 256]           = a1;
            out[ob + OSZ]           = a2;
            out[ob + OSZ + 256]     = a3;
            out[ob + 2 * OSZ]       = a4;
            out[ob + 2 * OSZ + 256] = a5;
        }
    }
}

extern "C" void kernel_launch(void* const* d_in, const int* in_sizes, int n_in,
                              void* d_out, int out_size) {
    const float* x   = (const float*)d_in[0];
    const int*   si1 = (const int*)d_in[1];
    const int*   si2 = (const int*)d_in[2];
    const int*   si3 = (const int*)d_in[3];
    float* out = (float*)d_out;

    const int smem_bytes = RING * QBUFB;      // 60928
    cudaFuncSetAttribute(addshift_kernel,
                         cudaFuncAttributeMaxDynamicSharedMemorySize, smem_bytes);

    addshift_kernel<<<GRID, THREADS, smem_bytes>>>(x, si1, si2, si3, out);
}